// round 11
// baseline (speedup 1.0000x reference)
#include <cuda_runtime.h>
#include <cuda_bf16.h>

// Problem constants
#define T_TYPES 27
#define N_NODES 16384
#define B_BATCH 256
#define IN_DIM  300
#define HID     128
#define OUT_DIM 64
#define TILE_B  8
#define N_TILES (B_BATCH / TILE_B)     // 32
#define ROW_F4  75                     // 300 floats = 75 float4

// Scratch: only segment bounds (tiny)
__device__ int g_bounds[T_TYPES * (B_BATCH + 1)];

typedef unsigned long long ull;

__device__ __forceinline__ ull fma2(ull a, ull b, ull c) {
    ull d;
    asm("fma.rn.f32x2 %0, %1, %2, %3;" : "=l"(d) : "l"(a), "l"(b), "l"(c));
    return d;
}
__device__ __forceinline__ ull add2(ull a, ull b) {
    ull d;
    asm("add.rn.f32x2 %0, %1, %2;" : "=l"(d) : "l"(a), "l"(b));
    return d;
}
__device__ __forceinline__ ull mul2(ull a, ull b) {
    ull d;
    asm("mul.rn.f32x2 %0, %1, %2;" : "=l"(d) : "l"(a), "l"(b));
    return d;
}
__device__ __forceinline__ ull pack2(float x) {
    ull d; asm("mov.b64 %0, {%1, %1};" : "=l"(d) : "f"(x)); return d;
}
__device__ __forceinline__ ull packab(float a, float b) {
    ull d; asm("mov.b64 %0, {%1, %2};" : "=l"(d) : "f"(a), "f"(b)); return d;
}
__device__ __forceinline__ void unpack2(ull v, float& lo, float& hi) {
    asm("mov.b64 {%0, %1}, %2;" : "=f"(lo), "=f"(hi) : "l"(v));
}
__device__ __forceinline__ ull relu2(ull v) {
    float lo, hi; unpack2(v, lo, hi);
    return packab(fmaxf(lo, 0.f), fmaxf(hi, 0.f));
}

__device__ __forceinline__ int lower_bound_i32(const int* s, int n, int v) {
    int lo = 0, hi = n;
    while (lo < hi) {
        int mid = (lo + hi) >> 1;
        if (s[mid] < v) lo = mid + 1; else hi = mid;
    }
    return lo;
}

// ---------------------------------------------------------------------------
// Kernel 0: precompute segment bounds. grid=27, block=256.
// ---------------------------------------------------------------------------
__global__ void bounds_kernel(const int* __restrict__ seg) {
    const int t = blockIdx.x;
    const int b = threadIdx.x;
    const int* s = seg + (size_t)t * N_NODES;
    g_bounds[t * (B_BATCH + 1) + b] = lower_bound_i32(s, N_NODES, b);
    if (b == 0) g_bounds[t * (B_BATCH + 1) + B_BATCH] = N_NODES;
}

// ---------------------------------------------------------------------------
// Fused kernel: grid=(32, 27) = 864 blocks (single wave), 128 threads.
// Pools 8 segments into smem [b][k], then runs the 2-layer MLP from smem.
// No global scratch, no atomics, no fences.
// ---------------------------------------------------------------------------
__global__ __launch_bounds__(128, 8)
void fused_kernel(const float* __restrict__ feat,
                  const float* __restrict__ W1,
                  const float* __restrict__ b1,
                  const float* __restrict__ W2,
                  const float* __restrict__ b2,
                  float* __restrict__ out) {
    const int t  = blockIdx.y;
    const int b0 = blockIdx.x * TILE_B;
    const int tid  = threadIdx.x;
    const int lane = tid & 31;
    const int w    = tid >> 5;

    __shared__ __align__(16) float s_pool[TILE_B * IN_DIM];      // 9600 B, [b][k]
    __shared__ __align__(16) char  s_aux[4 * ROW_F4 * 16];       // 4800 B: red, then ht

    const int* bnd = g_bounds + t * (B_BATCH + 1) + b0;
    const bool has2 = lane < (ROW_F4 - 64);   // lane < 11
    const ulonglong2 z2 = make_ulonglong2(0ull, 0ull);

    // ---------------- Phase 1: pool 8 segments ----------------
    #pragma unroll 1
    for (int i = 0; i < TILE_B; ++i) {
        const int lo  = bnd[i];
        const int cnt = bnd[i + 1] - lo;

        ull acc[6];
        #pragma unroll
        for (int q = 0; q < 6; ++q) acc[q] = 0ull;

        const ulonglong2* base =
            (const ulonglong2*)(feat + ((size_t)t * N_NODES + lo) * IN_DIM);
        int r = w;
        #pragma unroll 1
        for (; r + 8 < cnt; r += 12) {
            const ulonglong2* p0 = base + (size_t)r * ROW_F4;
            const ulonglong2* p1 = p0 + 4 * ROW_F4;
            const ulonglong2* p2 = p0 + 8 * ROW_F4;
            ulonglong2 v0 = __ldcs(p0 + lane);
            ulonglong2 v1 = __ldcs(p0 + 32 + lane);
            ulonglong2 v2 = has2 ? __ldcs(p0 + 64 + lane) : z2;
            ulonglong2 u0 = __ldcs(p1 + lane);
            ulonglong2 u1 = __ldcs(p1 + 32 + lane);
            ulonglong2 u2 = has2 ? __ldcs(p1 + 64 + lane) : z2;
            ulonglong2 q0 = __ldcs(p2 + lane);
            ulonglong2 q1 = __ldcs(p2 + 32 + lane);
            ulonglong2 q2 = has2 ? __ldcs(p2 + 64 + lane) : z2;
            acc[0] = add2(acc[0], v0.x); acc[1] = add2(acc[1], v0.y);
            acc[2] = add2(acc[2], v1.x); acc[3] = add2(acc[3], v1.y);
            acc[4] = add2(acc[4], v2.x); acc[5] = add2(acc[5], v2.y);
            acc[0] = add2(acc[0], u0.x); acc[1] = add2(acc[1], u0.y);
            acc[2] = add2(acc[2], u1.x); acc[3] = add2(acc[3], u1.y);
            acc[4] = add2(acc[4], u2.x); acc[5] = add2(acc[5], u2.y);
            acc[0] = add2(acc[0], q0.x); acc[1] = add2(acc[1], q0.y);
            acc[2] = add2(acc[2], q1.x); acc[3] = add2(acc[3], q1.y);
            acc[4] = add2(acc[4], q2.x); acc[5] = add2(acc[5], q2.y);
        }
        #pragma unroll 1
        for (; r < cnt; r += 4) {
            const ulonglong2* p0 = base + (size_t)r * ROW_F4;
            ulonglong2 v0 = __ldcs(p0 + lane);
            ulonglong2 v1 = __ldcs(p0 + 32 + lane);
            ulonglong2 v2 = has2 ? __ldcs(p0 + 64 + lane) : z2;
            acc[0] = add2(acc[0], v0.x); acc[1] = add2(acc[1], v0.y);
            acc[2] = add2(acc[2], v1.x); acc[3] = add2(acc[3], v1.y);
            acc[4] = add2(acc[4], v2.x); acc[5] = add2(acc[5], v2.y);
        }

        // cross-warp partials: red[w][col]
        {
            ulonglong2* red = (ulonglong2*)s_aux;
            red[w * ROW_F4 + lane]      = make_ulonglong2(acc[0], acc[1]);
            red[w * ROW_F4 + 32 + lane] = make_ulonglong2(acc[2], acc[3]);
            if (has2) red[w * ROW_F4 + 64 + lane] = make_ulonglong2(acc[4], acc[5]);
        }
        __syncthreads();

        if (tid < ROW_F4) {
            const ulonglong2* red = (const ulonglong2*)s_aux;
            ulonglong2 s0 = red[tid];
            ulonglong2 s1 = red[ROW_F4 + tid];
            ulonglong2 s2 = red[2 * ROW_F4 + tid];
            ulonglong2 s3 = red[3 * ROW_F4 + tid];
            const ull inv2 = pack2(1.0f / (float)max(cnt, 1));
            ull mx = mul2(add2(add2(s0.x, s1.x), add2(s2.x, s3.x)), inv2);
            ull my = mul2(add2(add2(s0.y, s1.y), add2(s2.y, s3.y)), inv2);
            *(ulonglong2*)&s_pool[i * IN_DIM + 4 * tid] = make_ulonglong2(mx, my);
        }
        __syncthreads();   // red reusable; s_pool row i visible
    }

    // ---------------- Phase 2: GEMM1 (j-packed f32x2) ----------------
    // thread = (jq, p): j-quad jq = tid&31 (j = 4*jq..4*jq+3), rows 2p, 2p+1 (p = warp)
    const int jq = tid & 31;
    const int p  = tid >> 5;

    ull a00, a01, a10, a11;   // a{jpair}{row-in-pair}
    {
        ulonglong2 bi = *(const ulonglong2*)&b1[t * HID + 4 * jq];
        a00 = bi.x; a01 = bi.x; a10 = bi.y; a11 = bi.y;
    }
    {
        const float* w1p = W1 + (size_t)t * IN_DIM * HID + 4 * jq;
        const float* r0 = &s_pool[(2 * p) * IN_DIM];
        const float* r1 = &s_pool[(2 * p + 1) * IN_DIM];

        ulonglong2 wc[4], wn[4];
        #pragma unroll
        for (int q = 0; q < 4; ++q)
            wc[q] = *(const ulonglong2*)(w1p + q * HID);

        for (int kg = 0; kg < IN_DIM / 4; ++kg) {
            const int kb = kg * 4;
            if (kg + 1 < IN_DIM / 4) {
                const float* wq = w1p + (kb + 4) * HID;
                #pragma unroll
                for (int q = 0; q < 4; ++q)
                    wn[q] = *(const ulonglong2*)(wq + q * HID);
            }
            #pragma unroll
            for (int q = 0; q < 4; ++q) {
                ull sv0 = pack2(r0[kb + q]);
                ull sv1 = pack2(r1[kb + q]);
                a00 = fma2(wc[q].x, sv0, a00);
                a01 = fma2(wc[q].x, sv1, a01);
                a10 = fma2(wc[q].y, sv0, a10);
                a11 = fma2(wc[q].y, sv1, a11);
            }
            #pragma unroll
            for (int q = 0; q < 4; ++q) wc[q] = wn[q];
        }
    }

    // relu + store ht[row][j] (overlay s_aux; safe: red last read before final sync)
    {
        float* ht = (float*)s_aux;
        *(ulonglong2*)&ht[(2 * p) * HID + 4 * jq] =
            make_ulonglong2(relu2(a00), relu2(a10));
        *(ulonglong2*)&ht[(2 * p + 1) * HID + 4 * jq] =
            make_ulonglong2(relu2(a01), relu2(a11));
    }
    __syncthreads();

    // ---------------- Phase 3: GEMM2 (packed over j-pairs) ----------------
    const int o  = tid & 63;
    const int rh = tid >> 6;               // rows rh*4 .. rh*4+3
    const float* ht = (const float*)s_aux;

    ull c0 = 0ull, c1 = 0ull, c2 = 0ull, c3 = 0ull;
    {
        const float* w2p = W2 + (size_t)t * HID * OUT_DIM + o;
        float wlo[4], whi[4], nlo[4], nhi[4];
        #pragma unroll
        for (int q = 0; q < 4; ++q) {
            wlo[q] = w2p[(2 * q) * OUT_DIM];
            whi[q] = w2p[(2 * q + 1) * OUT_DIM];
        }
        for (int jg = 0; jg < 16; ++jg) {      // 64 j-pairs / 4
            const int jb = jg * 4;
            if (jg + 1 < 16) {
                #pragma unroll
                for (int q = 0; q < 4; ++q) {
                    nlo[q] = w2p[(2 * (jb + 4 + q)) * OUT_DIM];
                    nhi[q] = w2p[(2 * (jb + 4 + q) + 1) * OUT_DIM];
                }
            }
            #pragma unroll
            for (int q = 0; q < 4; ++q) {
                const int jp = jb + q;
                ull wp = packab(wlo[q], whi[q]);
                c0 = fma2(wp, *(const ull*)&ht[(rh * 4 + 0) * HID + 2 * jp], c0);
                c1 = fma2(wp, *(const ull*)&ht[(rh * 4 + 1) * HID + 2 * jp], c1);
                c2 = fma2(wp, *(const ull*)&ht[(rh * 4 + 2) * HID + 2 * jp], c2);
                c3 = fma2(wp, *(const ull*)&ht[(rh * 4 + 3) * HID + 2 * jp], c3);
            }
            #pragma unroll
            for (int q = 0; q < 4; ++q) { wlo[q] = nlo[q]; whi[q] = nhi[q]; }
        }
    }

    // epilogue: horizontal add + bias, out[b, t, o]
    {
        const float bo = b2[t * OUT_DIM + o];
        float lo2, hi2;
        unpack2(c0, lo2, hi2);
        out[((size_t)(b0 + rh * 4 + 0) * T_TYPES + t) * OUT_DIM + o] = lo2 + hi2 + bo;
        unpack2(c1, lo2, hi2);
        out[((size_t)(b0 + rh * 4 + 1) * T_TYPES + t) * OUT_DIM + o] = lo2 + hi2 + bo;
        unpack2(c2, lo2, hi2);
        out[((size_t)(b0 + rh * 4 + 2) * T_TYPES + t) * OUT_DIM + o] = lo2 + hi2 + bo;
        unpack2(c3, lo2, hi2);
        out[((size_t)(b0 + rh * 4 + 3) * T_TYPES + t) * OUT_DIM + o] = lo2 + hi2 + bo;
    }
}

// ---------------------------------------------------------------------------
extern "C" void kernel_launch(void* const* d_in, const int* in_sizes, int n_in,
                              void* d_out, int out_size) {
    const float* feat = (const float*)d_in[0];
    const int*   seg  = (const int*)d_in[1];
    const float* W1   = (const float*)d_in[2];
    const float* b1   = (const float*)d_in[3];
    const float* W2   = (const float*)d_in[4];
    const float* b2   = (const float*)d_in[5];
    float* out = (float*)d_out;

    bounds_kernel<<<T_TYPES, B_BATCH>>>(seg);

    dim3 grid(N_TILES, T_TYPES);
    fused_kernel<<<grid, 128>>>(feat, W1, b1, W2, b2, out);
}

// round 12
// speedup vs baseline: 1.0364x; 1.0364x over previous
#include <cuda_runtime.h>
#include <cuda_bf16.h>
#include <cstdint>

// Problem constants
#define T_TYPES 27
#define N_NODES 16384
#define B_BATCH 256
#define IN_DIM  300
#define HID     128
#define OUT_DIM 64
#define TILE_B  8
#define N_TILES (B_BATCH / TILE_B)     // 32
#define ROW_BYTES 1200                 // 300 floats
#define CHUNK_ROWS 8
#define CHUNK_BYTES (CHUNK_ROWS * ROW_BYTES)   // 9600
#define ROW_ULL 150                    // 300 floats = 150 f32x2

__device__ int g_bounds[T_TYPES * (B_BATCH + 1)];

typedef unsigned long long ull;

__device__ __forceinline__ ull fma2(ull a, ull b, ull c) {
    ull d;
    asm("fma.rn.f32x2 %0, %1, %2, %3;" : "=l"(d) : "l"(a), "l"(b), "l"(c));
    return d;
}
__device__ __forceinline__ ull add2(ull a, ull b) {
    ull d;
    asm("add.rn.f32x2 %0, %1, %2;" : "=l"(d) : "l"(a), "l"(b));
    return d;
}
__device__ __forceinline__ ull mul2(ull a, ull b) {
    ull d;
    asm("mul.rn.f32x2 %0, %1, %2;" : "=l"(d) : "l"(a), "l"(b));
    return d;
}
__device__ __forceinline__ ull pack2(float x) {
    ull d; asm("mov.b64 %0, {%1, %1};" : "=l"(d) : "f"(x)); return d;
}
__device__ __forceinline__ ull packab(float a, float b) {
    ull d; asm("mov.b64 %0, {%1, %2};" : "=l"(d) : "f"(a), "f"(b)); return d;
}
__device__ __forceinline__ void unpack2(ull v, float& lo, float& hi) {
    asm("mov.b64 {%0, %1}, %2;" : "=f"(lo), "=f"(hi) : "l"(v));
}
__device__ __forceinline__ ull relu2(ull v) {
    float lo, hi; unpack2(v, lo, hi);
    return packab(fmaxf(lo, 0.f), fmaxf(hi, 0.f));
}

__device__ __forceinline__ uint32_t s2u(const void* p) {
    uint32_t a;
    asm("{ .reg .u64 t; cvta.to.shared.u64 t, %1; cvt.u32.u64 %0, t; }"
        : "=r"(a) : "l"(p));
    return a;
}
__device__ __forceinline__ void mbar_init(uint32_t m, uint32_t cnt) {
    asm volatile("mbarrier.init.shared.b64 [%0], %1;" :: "r"(m), "r"(cnt) : "memory");
}
__device__ __forceinline__ void mbar_expect_tx(uint32_t m, uint32_t bytes) {
    asm volatile("mbarrier.arrive.expect_tx.shared.b64 _, [%0], %1;"
                 :: "r"(m), "r"(bytes) : "memory");
}
__device__ __forceinline__ void bulk_g2s(uint32_t dst, const void* src,
                                         uint32_t bytes, uint32_t m) {
    asm volatile(
        "cp.async.bulk.shared::cta.global.mbarrier::complete_tx::bytes "
        "[%0], [%1], %2, [%3];"
        :: "r"(dst), "l"(src), "r"(bytes), "r"(m) : "memory");
}
__device__ __forceinline__ void mbar_wait(uint32_t m, int parity) {
    asm volatile(
        "{\n\t"
        ".reg .pred P;\n\t"
        "WAIT_%=:\n\t"
        "mbarrier.try_wait.parity.acquire.cta.shared::cta.b64 P, [%0], %1;\n\t"
        "@!P bra WAIT_%=;\n\t"
        "}" :: "r"(m), "r"(parity) : "memory");
}

// ---------------------------------------------------------------------------
// Kernel 0: segment bounds via histogram + scan. grid=27, block=256.
// ---------------------------------------------------------------------------
__global__ void bounds_kernel(const int* __restrict__ seg) {
    const int t = blockIdx.x;
    const int tid = threadIdx.x;
    __shared__ int hist[B_BATCH];

    hist[tid] = 0;
    __syncthreads();
    const int* s = seg + (size_t)t * N_NODES;
    for (int i = tid; i < N_NODES; i += B_BATCH)
        atomicAdd(&hist[s[i]], 1);
    __syncthreads();

    // inclusive scan (Hillis-Steele)
    for (int off = 1; off < B_BATCH; off <<= 1) {
        int u = (tid >= off) ? hist[tid - off] : 0;
        __syncthreads();
        hist[tid] += u;
        __syncthreads();
    }
    if (tid == 0) g_bounds[t * (B_BATCH + 1)] = 0;
    g_bounds[t * (B_BATCH + 1) + tid + 1] = hist[tid];
}

// ---------------------------------------------------------------------------
// Fused kernel: grid=(32, 27) = 864 blocks (single wave), 128 threads.
// Phase 1: cp.async.bulk double-buffered stream of the tile's contiguous row
//          range; per-thread f32x2 column accumulators; in-order segment
//          flushes into smem pool.
// Phase 2: 2-layer MLP from smem (j-packed f32x2), write out[b, t, o].
// ---------------------------------------------------------------------------
__global__ __launch_bounds__(128, 6)
void fused_kernel(const float* __restrict__ feat,
                  const float* __restrict__ W1,
                  const float* __restrict__ b1,
                  const float* __restrict__ W2,
                  const float* __restrict__ b2,
                  float* __restrict__ out) {
    const int t   = blockIdx.y;
    const int b0  = blockIdx.x * TILE_B;
    const int tid = threadIdx.x;

    __shared__ __align__(128) char  s_dma[2 * CHUNK_BYTES];   // 19200 B
    __shared__ __align__(16)  float s_pool[TILE_B * IN_DIM];  //  9600 B [b][k]
    __shared__ __align__(16)  float s_ht[TILE_B * HID];       //  4096 B [b][j]
    __shared__ __align__(8)   ull   s_mbar[2];
    __shared__ int s_bnd[TILE_B + 1];

    if (tid < TILE_B + 1)
        s_bnd[tid] = g_bounds[t * (B_BATCH + 1) + b0 + tid];
    if (tid == 0) {
        mbar_init(s2u(&s_mbar[0]), 1);
        mbar_init(s2u(&s_mbar[1]), 1);
    }
    __syncthreads();

    const int lo0 = s_bnd[0];
    const int total_rows = s_bnd[TILE_B] - lo0;
    const uint32_t total_bytes = (uint32_t)total_rows * ROW_BYTES;
    const int nch = (int)((total_bytes + CHUNK_BYTES - 1) / CHUNK_BYTES);

    const uint32_t dma_u32 = s2u(s_dma);
    const uint32_t mb0 = s2u(&s_mbar[0]);
    const uint32_t mb1 = s2u(&s_mbar[1]);
    const char* gsrc = (const char*)(feat + ((size_t)t * N_NODES + lo0) * IN_DIM);

    // ---------------- Phase 1: TMA-bulk streaming + segmented reduce ----------
    ull acc0 = 0ull, acc1 = 0ull;
    const bool hasB = tid < (ROW_ULL - 128);   // tid < 22 owns a 2nd column
    int cur = 0;                                // current segment in tile
    int cur_start = 0;
    int cur_end = s_bnd[1] - lo0;
    int ph0 = 0, ph1 = 0;

    // flush current segment's mean into s_pool, advance
    #define FLUSH() do {                                                        \
        const int cseg = cur;                                                   \
        const int ccnt = cur_end - cur_start;                                   \
        ull inv2 = pack2(1.0f / (float)max(ccnt, 1));                           \
        *(ull*)&s_pool[cseg * IN_DIM + 2 * tid] = mul2(acc0, inv2);             \
        if (hasB)                                                               \
            *(ull*)&s_pool[cseg * IN_DIM + 2 * (128 + tid)] = mul2(acc1, inv2); \
        acc0 = 0ull; acc1 = 0ull;                                               \
        cur++;                                                                  \
        cur_start = cur_end;                                                    \
        cur_end = (cur < TILE_B) ? (s_bnd[cur + 1] - lo0) : 0x7fffffff;         \
    } while (0)

    if (nch > 0 && tid == 0) {
        uint32_t bytes = min((uint32_t)CHUNK_BYTES, total_bytes);
        mbar_expect_tx(mb0, bytes);
        bulk_g2s(dma_u32, gsrc, bytes, mb0);
    }

    for (int c = 0; c < nch; ++c) {
        // issue chunk c+1 into the other buffer (it was released at end of c-1)
        if (tid == 0 && c + 1 < nch) {
            uint32_t off = (uint32_t)(c + 1) * CHUNK_BYTES;
            uint32_t bytes = min((uint32_t)CHUNK_BYTES, total_bytes - off);
            uint32_t m = ((c + 1) & 1) ? mb1 : mb0;
            mbar_expect_tx(m, bytes);
            bulk_g2s(dma_u32 + ((c + 1) & 1) * CHUNK_BYTES, gsrc + off, bytes, m);
        }
        // wait for chunk c
        if (c & 1) { mbar_wait(mb1, ph1); ph1 ^= 1; }
        else       { mbar_wait(mb0, ph0); ph0 ^= 1; }

        const char* buf = s_dma + (c & 1) * CHUNK_BYTES;
        const int r0 = c * CHUNK_ROWS;
        const int rows = min(CHUNK_ROWS, total_rows - r0);
        #pragma unroll
        for (int r = 0; r < CHUNK_ROWS; ++r) {
            if (r >= rows) break;
            const int gr = r0 + r;
            while (gr == cur_end) FLUSH();       // uniform across threads
            acc0 = add2(acc0, *(const ull*)(buf + r * ROW_BYTES + tid * 8));
            if (hasB)
                acc1 = add2(acc1, *(const ull*)(buf + r * ROW_BYTES + (128 + tid) * 8));
        }
        __syncthreads();   // all threads done reading buf (c&1) before reuse
    }
    while (cur < TILE_B) FLUSH();                // tail (incl. trailing empties)
    #undef FLUSH
    __syncthreads();

    // ---------------- Phase 2: GEMM1 (j-packed f32x2) ----------------
    // thread = (jq, p): j-quad jq = tid&31 (j = 4*jq..4*jq+3), rows 2p, 2p+1
    const int jq = tid & 31;
    const int p  = tid >> 5;

    ull a00, a01, a10, a11;
    {
        ulonglong2 bi = *(const ulonglong2*)&b1[t * HID + 4 * jq];
        a00 = bi.x; a01 = bi.x; a10 = bi.y; a11 = bi.y;
    }
    {
        const float* w1p = W1 + (size_t)t * IN_DIM * HID + 4 * jq;
        const float* r0 = &s_pool[(2 * p) * IN_DIM];
        const float* r1 = &s_pool[(2 * p + 1) * IN_DIM];

        ulonglong2 wc[4], wn[4];
        #pragma unroll
        for (int q = 0; q < 4; ++q)
            wc[q] = *(const ulonglong2*)(w1p + q * HID);

        for (int kg = 0; kg < IN_DIM / 4; ++kg) {
            const int kb = kg * 4;
            if (kg + 1 < IN_DIM / 4) {
                const float* wq = w1p + (kb + 4) * HID;
                #pragma unroll
                for (int q = 0; q < 4; ++q)
                    wn[q] = *(const ulonglong2*)(wq + q * HID);
            }
            #pragma unroll
            for (int q = 0; q < 4; ++q) {
                ull sv0 = pack2(r0[kb + q]);
                ull sv1 = pack2(r1[kb + q]);
                a00 = fma2(wc[q].x, sv0, a00);
                a01 = fma2(wc[q].x, sv1, a01);
                a10 = fma2(wc[q].y, sv0, a10);
                a11 = fma2(wc[q].y, sv1, a11);
            }
            #pragma unroll
            for (int q = 0; q < 4; ++q) wc[q] = wn[q];
        }
    }

    // relu + store ht[row][j]
    *(ulonglong2*)&s_ht[(2 * p) * HID + 4 * jq] =
        make_ulonglong2(relu2(a00), relu2(a10));
    *(ulonglong2*)&s_ht[(2 * p + 1) * HID + 4 * jq] =
        make_ulonglong2(relu2(a01), relu2(a11));
    __syncthreads();

    // ---------------- Phase 3: GEMM2 (packed over j-pairs) ----------------
    const int o  = tid & 63;
    const int rh = tid >> 6;               // rows rh*4 .. rh*4+3

    ull c0 = 0ull, c1 = 0ull, c2 = 0ull, c3 = 0ull;
    {
        const float* w2p = W2 + (size_t)t * HID * OUT_DIM + o;
        float wlo[4], whi[4], nlo[4], nhi[4];
        #pragma unroll
        for (int q = 0; q < 4; ++q) {
            wlo[q] = w2p[(2 * q) * OUT_DIM];
            whi[q] = w2p[(2 * q + 1) * OUT_DIM];
        }
        for (int jg = 0; jg < 16; ++jg) {      // 64 j-pairs / 4
            const int jb = jg * 4;
            if (jg + 1 < 16) {
                #pragma unroll
                for (int q = 0; q < 4; ++q) {
                    nlo[q] = w2p[(2 * (jb + 4 + q)) * OUT_DIM];
                    nhi[q] = w2p[(2 * (jb + 4 + q) + 1) * OUT_DIM];
                }
            }
            #pragma unroll
            for (int q = 0; q < 4; ++q) {
                const int jp = jb + q;
                ull wp = packab(wlo[q], whi[q]);
                c0 = fma2(wp, *(const ull*)&s_ht[(rh * 4 + 0) * HID + 2 * jp], c0);
                c1 = fma2(wp, *(const ull*)&s_ht[(rh * 4 + 1) * HID + 2 * jp], c1);
                c2 = fma2(wp, *(const ull*)&s_ht[(rh * 4 + 2) * HID + 2 * jp], c2);
                c3 = fma2(wp, *(const ull*)&s_ht[(rh * 4 + 3) * HID + 2 * jp], c3);
            }
            #pragma unroll
            for (int q = 0; q < 4; ++q) { wlo[q] = nlo[q]; whi[q] = nhi[q]; }
        }
    }

    // epilogue: horizontal add + bias, out[b, t, o]
    {
        const float bo = b2[t * OUT_DIM + o];
        float lo2, hi2;
        unpack2(c0, lo2, hi2);
        out[((size_t)(b0 + rh * 4 + 0) * T_TYPES + t) * OUT_DIM + o] = lo2 + hi2 + bo;
        unpack2(c1, lo2, hi2);
        out[((size_t)(b0 + rh * 4 + 1) * T_TYPES + t) * OUT_DIM + o] = lo2 + hi2 + bo;
        unpack2(c2, lo2, hi2);
        out[((size_t)(b0 + rh * 4 + 2) * T_TYPES + t) * OUT_DIM + o] = lo2 + hi2 + bo;
        unpack2(c3, lo2, hi2);
        out[((size_t)(b0 + rh * 4 + 3) * T_TYPES + t) * OUT_DIM + o] = lo2 + hi2 + bo;
    }
}

// ---------------------------------------------------------------------------
extern "C" void kernel_launch(void* const* d_in, const int* in_sizes, int n_in,
                              void* d_out, int out_size) {
    const float* feat = (const float*)d_in[0];
    const int*   seg  = (const int*)d_in[1];
    const float* W1   = (const float*)d_in[2];
    const float* b1   = (const float*)d_in[3];
    const float* W2   = (const float*)d_in[4];
    const float* b2   = (const float*)d_in[5];
    float* out = (float*)d_out;

    bounds_kernel<<<T_TYPES, B_BATCH>>>(seg);

    dim3 grid(N_TILES, T_TYPES);
    fused_kernel<<<grid, 128>>>(feat, W1, b1, W2, b2, out);
}